// round 3
// baseline (speedup 1.0000x reference)
#include <cuda_runtime.h>
#include <math.h>

// ProbabilisticMap: out[b][x][y][t] = N(p; mean(b,t), cov(b,t)) for a Bezier
// mixture of 8 control-point Gaussians.
//
// Shapes: cp_means (8,128,2), cp_covariances (8,128,2,2), out (128,64,64,50) fp32.
//
// Strategy: per-(b,t) params (6 useful floats, padded to 7 for bank-conflict-free
// shared reads) computed once per block by threads 0..49, then 26.2M streaming
// element evaluations with coalesced __stcs writes.

#define MAP_W 64
#define MAP_H 64
#define MAP_T 50
#define NUM_CP 8
#define BATCH 128

#define TPB 256
#define ELEMS_PER_THREAD 4
#define EPB (TPB * ELEMS_PER_THREAD)            // 1024 elements per block
#define ELEMS_PER_B (MAP_W * MAP_H * MAP_T)     // 204800, divisible by EPB
#define BLOCKS_PER_B (ELEMS_PER_B / EPB)        // 200
#define TOTAL_ELEMS (BATCH * ELEMS_PER_B)       // 26,214,400
#define NUM_BLOCKS (TOTAL_ELEMS / EPB)          // 25,600

__global__ __launch_bounds__(TPB)
void probmap_kernel(const float* __restrict__ cp_means,
                    const float* __restrict__ cp_covs,
                    float* __restrict__ out)
{
    // Per-t params for this block's batch b:
    // [0]=mean_x [1]=mean_y [2]=-0.5*d/det [3]=+0.5*(b+c)/det [4]=-0.5*a/det
    // [5]=1/(2*pi*sqrt(det)) [6]=pad
    __shared__ float sp[MAP_T * 7];

    const int tid = threadIdx.x;
    const int b   = blockIdx.x / BLOCKS_PER_B;

    if (tid < MAP_T) {
        const float tt = (float)tid * (1.0f / (float)(MAP_T - 1));
        const float u  = 1.0f - tt;
        const float C[NUM_CP] = {1.f, 7.f, 21.f, 35.f, 35.f, 21.f, 7.f, 1.f};

        // powers of (1-t): up[k] = u^k
        float up[NUM_CP];
        up[0] = 1.0f;
#pragma unroll
        for (int i = 1; i < NUM_CP; i++) up[i] = up[i - 1] * u;

        float mx = 0.f, my = 0.f;
        float ca = 0.f, cb = 0.f, cc = 0.f, cd = 0.f;
        float tp = 1.0f;  // t^i
#pragma unroll
        for (int i = 0; i < NUM_CP; i++) {
            const float bas = C[i] * tp * up[NUM_CP - 1 - i];
            tp *= tt;
            const float b2 = bas * bas;
            const float* m  = cp_means + (i * BATCH + b) * 2;   // warp-broadcast
            const float* cv = cp_covs  + (i * BATCH + b) * 4;
            mx = fmaf(bas, m[0], mx);
            my = fmaf(bas, m[1], my);
            ca = fmaf(b2, cv[0], ca);
            cb = fmaf(b2, cv[1], cb);
            cc = fmaf(b2, cv[2], cc);
            cd = fmaf(b2, cv[3], cd);
        }
        const float det     = ca * cd - cb * cc;
        const float inv_det = 1.0f / det;
        float* p = sp + tid * 7;
        p[0] = mx;
        p[1] = my;
        p[2] = -0.5f * cd * inv_det;
        p[3] =  0.5f * (cb + cc) * inv_det;
        p[4] = -0.5f * ca * inv_det;
        p[5] = 0.15915494309189535f * rsqrtf(det);   // 1/(2*pi*sqrt(det))
    }
    __syncthreads();

    const int base = blockIdx.x * EPB;
#pragma unroll
    for (int e = 0; e < ELEMS_PER_THREAD; e++) {
        const int idx = base + tid + e * TPB;           // lane-consecutive
        const unsigned pix = (unsigned)idx / (unsigned)MAP_T;   // magic-mul div
        const int t = idx - (int)pix * MAP_T;
        const float x = (float)((pix >> 6) & 63u);
        const float y = (float)(pix & 63u);

        const float* p = sp + t * 7;                    // stride-7: conflict-free
        const float dx = x - p[0];
        const float dy = y - p[1];
        // exponent = e0*dx^2 + e1*dx*dy + e2*dy^2  (already includes -0.5/det)
        const float q = fmaf(p[2] * dx, dx, fmaf(p[3] * dx, dy, p[4] * dy * dy));
        __stcs(out + idx, __expf(q) * p[5]);            // streaming store, no L2 reuse
    }
}

extern "C" void kernel_launch(void* const* d_in, const int* in_sizes, int n_in,
                              void* d_out, int out_size)
{
    const float* cp_means = (const float*)d_in[0];  // (8,128,2)
    const float* cp_covs  = (const float*)d_in[1];  // (8,128,2,2)
    float* out = (float*)d_out;                     // (128,64,64,50)
    (void)in_sizes; (void)n_in; (void)out_size;

    probmap_kernel<<<NUM_BLOCKS, TPB>>>(cp_means, cp_covs, out);
}

// round 5
// speedup vs baseline: 1.4784x; 1.4784x over previous
#include <cuda_runtime.h>
#include <math.h>

// ProbabilisticMap: out[b][x][y][t] = N((x,y); mean(b,t), cov(b,t)) for a
// Bezier mixture of 8 control-point Gaussians.
// Shapes: cp_means (8,128,2), cp_covariances (8,128,2,2), out (128,64,64,50) fp32.
//
// R5 (= R4 re-bench after infra flake): instruction-diet version. Per element:
//   LDS.64 (mean) + LDS.128 (quad coeffs, pre-scaled by -0.5*log2e/det with the
//   normalizer folded into the exponent) + 2 I2F + 2 FADD + 2 FMUL + 3 FMA +
//   1 MUFU.EX2 + STG.32 + branchless incremental (t,pix) bookkeeping.
// Shared arrays are float2/float4 -> conflict-free for lane-consecutive t.

#define MAP_W 64
#define MAP_H 64
#define MAP_T 50
#define NUM_CP 8
#define BATCH 128

#define TPB 256
#define EPT 8                                   // elements per thread
#define EPB (TPB * EPT)                         // 2048 elements per block
#define ELEMS_PER_B (MAP_W * MAP_H * MAP_T)     // 204800
#define BLOCKS_PER_B (ELEMS_PER_B / EPB)        // 100
#define TOTAL_ELEMS (BATCH * ELEMS_PER_B)       // 26,214,400
#define NUM_BLOCKS (TOTAL_ELEMS / EPB)          // 12,800

__device__ __forceinline__ float ex2(float x) {
    float r;
    asm("ex2.approx.ftz.f32 %0, %1;" : "=f"(r) : "f"(x));
    return r;
}

__global__ __launch_bounds__(TPB)
void probmap_kernel(const float* __restrict__ cp_means,
                    const float* __restrict__ cp_covs,
                    float* __restrict__ out)
{
    __shared__ float2 sM[MAP_T];   // (mean_x, mean_y)
    __shared__ float4 sQ[MAP_T];   // (c0, c1, c2, ls): exponent-space coeffs

    const int tid = threadIdx.x;
    const int b   = blockIdx.x / BLOCKS_PER_B;

    if (tid < MAP_T) {
        const float tt = (float)tid * (1.0f / (float)(MAP_T - 1));
        const float u  = 1.0f - tt;
        const float C[NUM_CP] = {1.f, 7.f, 21.f, 35.f, 35.f, 21.f, 7.f, 1.f};

        float up[NUM_CP];
        up[0] = 1.0f;
#pragma unroll
        for (int i = 1; i < NUM_CP; i++) up[i] = up[i - 1] * u;

        float mx = 0.f, my = 0.f;
        float ca = 0.f, cb = 0.f, cc = 0.f, cd = 0.f;
        float tp = 1.0f;
#pragma unroll
        for (int i = 0; i < NUM_CP; i++) {
            const float bas = C[i] * tp * up[NUM_CP - 1 - i];
            tp *= tt;
            const float b2 = bas * bas;
            const float* m  = cp_means + (i * BATCH + b) * 2;   // warp-broadcast LDG
            const float* cv = cp_covs  + (i * BATCH + b) * 4;
            mx = fmaf(bas, m[0], mx);
            my = fmaf(bas, m[1], my);
            ca = fmaf(b2, cv[0], ca);
            cb = fmaf(b2, cv[1], cb);
            cc = fmaf(b2, cv[2], cc);
            cd = fmaf(b2, cv[3], cd);
        }
        const float det     = ca * cd - cb * cc;
        const float inv_det = 1.0f / det;
        const float HL2E    = 0.5f * 1.4426950408889634f;   // 0.5*log2(e)
        // exponent-space coefficients: out = exp2(c0*dx^2 + c1*dx*dy + c2*dy^2 + ls)
        const float c0 = -HL2E * cd * inv_det;
        const float c1 =  HL2E * (cb + cc) * inv_det;
        const float c2 = -HL2E * ca * inv_det;
        // ls = -0.5*log2((2*pi)^2 * det)
        const float ls = -0.5f * __log2f(39.478417604357434f * det);
        sM[tid] = make_float2(mx, my);
        sQ[tid] = make_float4(c0, c1, c2, ls);
    }
    __syncthreads();

    const int idx0 = blockIdx.x * EPB + tid;
    const unsigned t0   = (unsigned)idx0 % (unsigned)MAP_T;  // one magic-div per thread
    const unsigned pix0 = (unsigned)idx0 / (unsigned)MAP_T;
    float* __restrict__ outp = out + idx0;

    // stride TPB=256 between a thread's elements: t advances 6 (mod 50), pix by 5(+wrap).
#pragma unroll
    for (int e = 0; e < EPT; e++) {
        unsigned te = t0 + 6u * (unsigned)e;     // 6e <= 42 -> at most one wrap
        unsigned pe = pix0 + 5u * (unsigned)e;
        if (te >= (unsigned)MAP_T) { te -= (unsigned)MAP_T; pe += 1u; }

        const float2 m = sM[te];                 // LDS.64, conflict-free
        const float4 q = sQ[te];                 // LDS.128, conflict-free

        const float x  = (float)((pe >> 6) & 63u);
        const float y  = (float)(pe & 63u);
        const float dx = x - m.x;
        const float dy = y - m.y;

        float s = fmaf(q.x, dx, q.y * dy);       // c0*dx + c1*dy
        s       = fmaf(dx, s, q.w);              // *dx + ls
        s       = fmaf(q.z * dy, dy, s);         // + c2*dy^2
        __stcs(outp + e * TPB, ex2(s));          // streaming store, no L2 reuse
    }
}

extern "C" void kernel_launch(void* const* d_in, const int* in_sizes, int n_in,
                              void* d_out, int out_size)
{
    const float* cp_means = (const float*)d_in[0];  // (8,128,2)
    const float* cp_covs  = (const float*)d_in[1];  // (8,128,2,2)
    float* out = (float*)d_out;                     // (128,64,64,50)
    (void)in_sizes; (void)n_in; (void)out_size;

    probmap_kernel<<<NUM_BLOCKS, TPB>>>(cp_means, cp_covs, out);
}

// round 7
// speedup vs baseline: 1.9922x; 1.3475x over previous
#include <cuda_runtime.h>
#include <math.h>

// ProbabilisticMap: out[b][x][y][t] = N((x,y); mean(b,t), cov(b,t)) for a
// Bezier mixture of 8 control-point Gaussians.
// Shapes: cp_means (8,128,2), cp_covariances (8,128,2,2), out (128,64,64,50) fp32.
//
// R7 (= R6 re-bench after infra flake): warp-uniform-t restructure.
//   Block = one batch b x 128 consecutive pixels (grid 128*32 = 4096 blocks).
//   Phase 0: threads 192..241 build per-t params (mean, exponent-space quad
//            coeffs, log-space normalizer) in SMEM.
//   Phase 1: warp w evaluates t = w, w+8, ... All lanes share t -> param LDS is
//            broadcast and reused across 4 pixels/lane; (x,y) fixed per lane so
//            the hot loop has ZERO integer/index work. Results go to a 128x50
//            SMEM tile laid out identically to the output image.
//   Phase 2: drain tile with coalesced LDS.128 + __stcs float4 stores.

#define MAP_W 64
#define MAP_H 64
#define MAP_T 50
#define NUM_CP 8
#define BATCH 128

#define TPB 256
#define PX_PER_BLOCK 128
#define FLOATS_PER_BLOCK (PX_PER_BLOCK * MAP_T)     // 6400
#define VEC4_PER_BLOCK   (FLOATS_PER_BLOCK / 4)     // 1600
#define BLOCKS_PER_B     ((MAP_W * MAP_H) / PX_PER_BLOCK)  // 32
#define NUM_BLOCKS       (BATCH * BLOCKS_PER_B)     // 4096

__device__ __forceinline__ float ex2(float x) {
    float r;
    asm("ex2.approx.ftz.f32 %0, %1;" : "=f"(r) : "f"(x));
    return r;
}

__global__ __launch_bounds__(TPB)
void probmap_kernel(const float* __restrict__ cp_means,
                    const float* __restrict__ cp_covs,
                    float* __restrict__ out)
{
    __shared__ float4 sP4[MAP_T];                // (mx, my, c0, c1)
    __shared__ float2 sP2[MAP_T];                // (c2, ls)
    __shared__ __align__(16) float tile[FLOATS_PER_BLOCK];  // 25.6 KB, == output layout

    const int tid = threadIdx.x;
    const int b   = blockIdx.x >> 5;             // batch index
    const int p0  = (blockIdx.x & 31) * PX_PER_BLOCK;  // first pixel of this block

    // ---- Phase 0: per-t parameters (threads 192..241 = warps 6,7, which have
    //      the lighter phase-1 load) ----
    const int tp = tid - 192;
    if ((unsigned)tp < (unsigned)MAP_T) {
        const float tt = (float)tp * (1.0f / (float)(MAP_T - 1));
        const float u  = 1.0f - tt;
        const float C[NUM_CP] = {1.f, 7.f, 21.f, 35.f, 35.f, 21.f, 7.f, 1.f};

        float up[NUM_CP];
        up[0] = 1.0f;
#pragma unroll
        for (int i = 1; i < NUM_CP; i++) up[i] = up[i - 1] * u;

        float mx = 0.f, my = 0.f;
        float ca = 0.f, cb = 0.f, cc = 0.f, cd = 0.f;
        float t_pow = 1.0f;
#pragma unroll
        for (int i = 0; i < NUM_CP; i++) {
            const float bas = C[i] * t_pow * up[NUM_CP - 1 - i];
            t_pow *= tt;
            const float b2 = bas * bas;
            const float* m  = cp_means + (i * BATCH + b) * 2;   // warp-broadcast LDG
            const float* cv = cp_covs  + (i * BATCH + b) * 4;
            mx = fmaf(bas, m[0], mx);
            my = fmaf(bas, m[1], my);
            ca = fmaf(b2, cv[0], ca);
            cb = fmaf(b2, cv[1], cb);
            cc = fmaf(b2, cv[2], cc);
            cd = fmaf(b2, cv[3], cd);
        }
        const float det     = ca * cd - cb * cc;
        const float inv_det = 1.0f / det;
        const float HL2E    = 0.5f * 1.4426950408889634f;     // 0.5*log2(e)
        // exponent-space: out = exp2(c0*dx^2 + c1*dx*dy + c2*dy^2 + ls)
        const float c0 = -HL2E * cd * inv_det;
        const float c1 =  HL2E * (cb + cc) * inv_det;
        const float c2 = -HL2E * ca * inv_det;
        const float ls = -0.5f * __log2f(39.478417604357434f * det); // -0.5*log2((2pi)^2 det)
        sP4[tp] = make_float4(mx, my, c0, c1);
        sP2[tp] = make_float2(c2, ls);
    }
    __syncthreads();

    // ---- Phase 1: warp-uniform t, 4 pixels per lane, zero hot-loop index math ----
    const int w = tid >> 5;
    const int l = tid & 31;

    float xf[4], yf[4];
#pragma unroll
    for (int c = 0; c < 4; c++) {
        const int p = p0 + l + 32 * c;           // global pixel
        xf[c] = (float)(p >> 6);
        yf[c] = (float)(p & 63);
    }

    for (int t = w; t < MAP_T; t += 8) {         // warps 0,1: 7 iters; 2..7: 6
        const float4 q4 = sP4[t];                // broadcast LDS (1 wavefront)
        const float2 q2 = sP2[t];
        float* dst = tile + l * MAP_T + t;       // lane-local column, +c*32*50 per pixel
#pragma unroll
        for (int c = 0; c < 4; c++) {
            const float dx = xf[c] - q4.x;
            const float dy = yf[c] - q4.y;
            float s = fmaf(q4.w, dy, q4.z * dx); // c0*dx + c1*dy
            s       = fmaf(s, dx, q2.y);         // *dx + ls
            s       = fmaf(q2.x * dy, dy, s);    // + c2*dy^2
            dst[c * 32 * MAP_T] = ex2(s);        // STS.32 (2-way bank conflict, cheap)
        }
    }
    __syncthreads();

    // ---- Phase 2: coalesced vectorized drain (tile layout == output layout) ----
    const float4* t4 = (const float4*)tile;
    float4* o4 = (float4*)out + (size_t)blockIdx.x * VEC4_PER_BLOCK;
#pragma unroll
    for (int k = 0; k < 6; k++) {                // 6*256 = 1536 float4s
        __stcs(&o4[tid + k * TPB], t4[tid + k * TPB]);
    }
    if (tid < VEC4_PER_BLOCK - 6 * TPB) {        // remaining 64 float4s
        __stcs(&o4[tid + 6 * TPB], t4[tid + 6 * TPB]);
    }
}

extern "C" void kernel_launch(void* const* d_in, const int* in_sizes, int n_in,
                              void* d_out, int out_size)
{
    const float* cp_means = (const float*)d_in[0];  // (8,128,2)
    const float* cp_covs  = (const float*)d_in[1];  // (8,128,2,2)
    float* out = (float*)d_out;                     // (128,64,64,50)
    (void)in_sizes; (void)n_in; (void)out_size;

    probmap_kernel<<<NUM_BLOCKS, TPB>>>(cp_means, cp_covs, out);
}

// round 8
// speedup vs baseline: 2.1051x; 1.0567x over previous
#include <cuda_runtime.h>
#include <math.h>

// ProbabilisticMap: out[b][x][y][t] = N((x,y); mean(b,t), cov(b,t)) for a
// Bezier mixture of 8 control-point Gaussians.
// Shapes: cp_means (8,128,2), cp_covariances (8,128,2,2), out (128,64,64,50) fp32.
//
// R8: R7 (warp-uniform-t, SMEM tile transpose) + TMA bulk-store drain.
//   Phase 2's per-thread LDS.128+STG.128 drain is replaced by a single
//   cp.async.bulk.global.shared::cta per block: the async engine streams the
//   25.6 KB tile (already in exact output layout) to GMEM with zero L1
//   wavefronts from threads and zero issue slots.

#define MAP_W 64
#define MAP_H 64
#define MAP_T 50
#define NUM_CP 8
#define BATCH 128

#define TPB 256
#define PX_PER_BLOCK 128
#define FLOATS_PER_BLOCK (PX_PER_BLOCK * MAP_T)     // 6400
#define TILE_BYTES       (FLOATS_PER_BLOCK * 4)     // 25600, multiple of 16
#define BLOCKS_PER_B     ((MAP_W * MAP_H) / PX_PER_BLOCK)  // 32
#define NUM_BLOCKS       (BATCH * BLOCKS_PER_B)     // 4096

__device__ __forceinline__ float ex2(float x) {
    float r;
    asm("ex2.approx.ftz.f32 %0, %1;" : "=f"(r) : "f"(x));
    return r;
}

__device__ __forceinline__ unsigned smem_u32(const void* p) {
    unsigned a;
    asm("{ .reg .u64 t; cvta.to.shared.u64 t, %1; cvt.u32.u64 %0, t; }"
        : "=r"(a) : "l"(p));
    return a;
}

__global__ __launch_bounds__(TPB)
void probmap_kernel(const float* __restrict__ cp_means,
                    const float* __restrict__ cp_covs,
                    float* __restrict__ out)
{
    __shared__ float4 sP4[MAP_T];                // (mx, my, c0, c1)
    __shared__ float2 sP2[MAP_T];                // (c2, ls)
    __shared__ __align__(16) float tile[FLOATS_PER_BLOCK];  // 25.6 KB, == output layout

    const int tid = threadIdx.x;
    const int b   = blockIdx.x >> 5;             // batch index
    const int p0  = (blockIdx.x & 31) * PX_PER_BLOCK;  // first pixel of this block

    // ---- Phase 0: per-t parameters (threads 192..241 = warps 6,7, the warps
    //      with the lighter phase-1 load) ----
    const int tp = tid - 192;
    if ((unsigned)tp < (unsigned)MAP_T) {
        const float tt = (float)tp * (1.0f / (float)(MAP_T - 1));
        const float u  = 1.0f - tt;
        const float C[NUM_CP] = {1.f, 7.f, 21.f, 35.f, 35.f, 21.f, 7.f, 1.f};

        float up[NUM_CP];
        up[0] = 1.0f;
#pragma unroll
        for (int i = 1; i < NUM_CP; i++) up[i] = up[i - 1] * u;

        float mx = 0.f, my = 0.f;
        float ca = 0.f, cb = 0.f, cc = 0.f, cd = 0.f;
        float t_pow = 1.0f;
#pragma unroll
        for (int i = 0; i < NUM_CP; i++) {
            const float bas = C[i] * t_pow * up[NUM_CP - 1 - i];
            t_pow *= tt;
            const float b2 = bas * bas;
            const float* m  = cp_means + (i * BATCH + b) * 2;   // warp-broadcast LDG
            const float* cv = cp_covs  + (i * BATCH + b) * 4;
            mx = fmaf(bas, m[0], mx);
            my = fmaf(bas, m[1], my);
            ca = fmaf(b2, cv[0], ca);
            cb = fmaf(b2, cv[1], cb);
            cc = fmaf(b2, cv[2], cc);
            cd = fmaf(b2, cv[3], cd);
        }
        const float det     = ca * cd - cb * cc;
        const float inv_det = 1.0f / det;
        const float HL2E    = 0.5f * 1.4426950408889634f;     // 0.5*log2(e)
        // exponent-space: out = exp2(c0*dx^2 + c1*dx*dy + c2*dy^2 + ls)
        const float c0 = -HL2E * cd * inv_det;
        const float c1 =  HL2E * (cb + cc) * inv_det;
        const float c2 = -HL2E * ca * inv_det;
        const float ls = -0.5f * __log2f(39.478417604357434f * det); // -0.5*log2((2pi)^2 det)
        sP4[tp] = make_float4(mx, my, c0, c1);
        sP2[tp] = make_float2(c2, ls);
    }
    __syncthreads();

    // ---- Phase 1: warp-uniform t, 4 pixels per lane, zero hot-loop index math ----
    const int w = tid >> 5;
    const int l = tid & 31;

    float xf[4], yf[4];
#pragma unroll
    for (int c = 0; c < 4; c++) {
        const int p = p0 + l + 32 * c;           // global pixel
        xf[c] = (float)(p >> 6);
        yf[c] = (float)(p & 63);
    }

    for (int t = w; t < MAP_T; t += 8) {         // warps 0,1: 7 iters; 2..7: 6
        const float4 q4 = sP4[t];                // broadcast LDS (1 wavefront)
        const float2 q2 = sP2[t];
        float* dst = tile + l * MAP_T + t;       // lane-local column, +c*32*50 per pixel
#pragma unroll
        for (int c = 0; c < 4; c++) {
            const float dx = xf[c] - q4.x;
            const float dy = yf[c] - q4.y;
            float s = fmaf(q4.w, dy, q4.z * dx); // c0*dx + c1*dy
            s       = fmaf(s, dx, q2.y);         // *dx + ls
            s       = fmaf(q2.x * dy, dy, s);    // + c2*dy^2
            dst[c * 32 * MAP_T] = ex2(s);        // STS.32 (2-way bank conflict)
        }
    }
    __syncthreads();

    // ---- Phase 2: async bulk drain (tile layout == output layout) ----
    if (tid == 0) {
        asm volatile("fence.proxy.async;" ::: "memory");   // STS -> async proxy
        char* gdst = (char*)out + (size_t)blockIdx.x * TILE_BYTES;
        const unsigned ssrc = smem_u32(tile);
        asm volatile(
            "cp.async.bulk.global.shared::cta.bulk_group [%0], [%1], %2;"
            :: "l"(gdst), "r"(ssrc), "r"((unsigned)TILE_BYTES) : "memory");
        asm volatile("cp.async.bulk.commit_group;" ::: "memory");
        // Wait for the SMEM reads to finish before the CTA may retire.
        asm volatile("cp.async.bulk.wait_group.read 0;" ::: "memory");
    }
    // Other threads exit; CTA (and its SMEM) persists until tid 0 finishes.
}

extern "C" void kernel_launch(void* const* d_in, const int* in_sizes, int n_in,
                              void* d_out, int out_size)
{
    const float* cp_means = (const float*)d_in[0];  // (8,128,2)
    const float* cp_covs  = (const float*)d_in[1];  // (8,128,2,2)
    float* out = (float*)d_out;                     // (128,64,64,50)
    (void)in_sizes; (void)n_in; (void)out_size;

    probmap_kernel<<<NUM_BLOCKS, TPB>>>(cp_means, cp_covs, out);
}